// round 13
// baseline (speedup 1.0000x reference)
#include <cuda_runtime.h>
#include <cuda_fp16.h>
#include <cstdint>

#define HW 256
#define PLANE (HW * HW)
#define TILE 8
#define NT 544               // warp0 = scanner; warps 1..16 = 512 loaders
#define SQS 293              // packed float4 row stride (odd => STS conflict-free)
#define NTILES (HW / TILE)   // 32
#define PBUF (TILE * SQS)    // float4s per packed buffer

// Per-(plane,dir) fp16 scratch, plane index = bc*4 + dir (67 MB).
// dirs 0,1 (horizontal) stored TRANSPOSED [w][h]; dirs 2,3 natural [h][w].
__device__ __half g_scratch[512 * PLANE];

struct alignas(16) H8 { __half2 p0, p1, p2, p3; };
struct Stage { float4 M, A, B, C; };      // one 16B group x 4 arrays = 16 regs

// k -> conflict-free smem slot within a packed step-row
__device__ __forceinline__ int kmap(int k) { return 9 * (k >> 3) + (k & 7); }

__device__ __forceinline__ float4 gate_pack(float m, float g1, float g2, float g3) {
    float s = fabsf(g1) + fabsf(g2) + fabsf(g3) + 1e-7f;
    float r = (s >= 1.f) ? __fdividef(1.f, s) : 1.f;
    float a = g1 * r, b = g2 * r, c = g3 * r;
    return make_float4((1.f - a - b - c) * m, a, b, c);
}

// 4 independent LDG.128s (front-batched by ptxas).
__device__ __forceinline__ void ldg_tile(Stage& s, int ga,
    const float* __restrict__ mb, const float* __restrict__ g1b,
    const float* __restrict__ g2b, const float* __restrict__ g3b)
{
    s.M = *(const float4*)(mb  + ga);
    s.A = *(const float4*)(g1b + ga);
    s.B = *(const float4*)(g2b + ga);
    s.C = *(const float4*)(g3b + ga);
}

// Normalize + transpose-pack one staged group into a packed smem buffer.
__device__ __forceinline__ void sts_tile(const Stage& s, float4* packed, bool horiz, int g)
{
    const float* Mp = (const float*)&s.M;
    const float* Ap = (const float*)&s.A;
    const float* Bp = (const float*)&s.B;
    const float* Cp = (const float*)&s.C;
    if (horiz) {
        int k = g >> 1, hf = g & 1;
        int km = kmap(k), L0 = 4 * hf;
        #pragma unroll
        for (int j = 0; j < 4; ++j)
            packed[(L0 + j) * SQS + km] = gate_pack(Mp[j], Ap[j], Bp[j], Cp[j]);
    } else {
        int L = g >> 6, k4 = g & 63;
        float4* row = packed + L * SQS;
        #pragma unroll
        for (int j = 0; j < 4; ++j)
            row[kmap(4 * k4 + j)] = gate_pack(Mp[j], Ap[j], Bp[j], Cp[j]);
    }
}

// Scanner: one 8-step tile over the full 256-wide k-line, warp-synchronous.
__device__ __forceinline__ void scan_tile(
    const float4* __restrict__ pk, float* __restrict__ h, __half* __restrict__ scr,
    int base0, bool rev, int lane)
{
    #pragma unroll
    for (int st = 0; st < TILE; ++st) {
        int L = rev ? (TILE - 1 - st) : st;
        const float4* row = pk + L * SQS + 9 * lane;
        float4 q0 = row[0], q1 = row[1], q2 = row[2], q3 = row[3];
        float4 q4 = row[4], q5 = row[5], q6 = row[6], q7 = row[7];
        float hm = __shfl_up_sync(0xffffffffu, h[7], 1);
        float hp = __shfl_down_sync(0xffffffffu, h[0], 1);
        if (lane == 0)  hm = 0.f;
        if (lane == 31) hp = 0.f;
        float hn[8];
        hn[0] = fmaf(q0.w, h[1], fmaf(q0.z, h[0], fmaf(q0.y, hm,   q0.x)));
        hn[1] = fmaf(q1.w, h[2], fmaf(q1.z, h[1], fmaf(q1.y, h[0], q1.x)));
        hn[2] = fmaf(q2.w, h[3], fmaf(q2.z, h[2], fmaf(q2.y, h[1], q2.x)));
        hn[3] = fmaf(q3.w, h[4], fmaf(q3.z, h[3], fmaf(q3.y, h[2], q3.x)));
        hn[4] = fmaf(q4.w, h[5], fmaf(q4.z, h[4], fmaf(q4.y, h[3], q4.x)));
        hn[5] = fmaf(q5.w, h[6], fmaf(q5.z, h[5], fmaf(q5.y, h[4], q5.x)));
        hn[6] = fmaf(q6.w, h[7], fmaf(q6.z, h[6], fmaf(q6.y, h[5], q6.x)));
        hn[7] = fmaf(q7.w, hp,   fmaf(q7.z, h[7], fmaf(q7.y, h[6], q7.x)));
        #pragma unroll
        for (int e = 0; e < 8; ++e) h[e] = hn[e];
        H8 v;
        v.p0 = __floats2half2_rn(h[0], h[1]);
        v.p1 = __floats2half2_rn(h[2], h[3]);
        v.p2 = __floats2half2_rn(h[4], h[5]);
        v.p3 = __floats2half2_rn(h[6], h[7]);
        *(H8*)(scr + (base0 + L) * HW + 8 * lane) = v;   // 16B coalesced
    }
}

__global__ __launch_bounds__(NT, 2) void spn_scan(
    const float* __restrict__ x,
    const float* __restrict__ mask)
{
    extern __shared__ float4 packed[];                 // [2][TILE][SQS]

    const int tid = threadIdx.x;
    const int blk = blockIdx.x;
    const int dir = blk & 3;                           // interleave dirs -> mask L2 reuse
    const int bc  = blk >> 2;
    const int b   = bc >> 5;
    const int c   = bc & 31;
    const bool horiz = (dir < 2);
    const bool rev   = (dir & 1);

    const float* mb  = mask + (size_t)bc * PLANE;
    const float* g1b = x + (size_t)(b * 384 + (3 * dir + 0) * 32 + c) * PLANE;
    const float* g2b = x + (size_t)(b * 384 + (3 * dir + 1) * 32 + c) * PLANE;
    const float* g3b = x + (size_t)(b * 384 + (3 * dir + 2) * 32 + c) * PLANE;
    __half* scr = g_scratch + (size_t)blk * PLANE;

    const int lane = tid & 31;
    const int g    = tid - 32;                         // loader group 0..511 (scanner: <0)

    auto tbase = [&](int t) { return rev ? (HW - TILE - TILE * t) : (TILE * t); };
    // gmem offset of group g within the tile starting at base0
    auto gaddr = [&](int base0) {
        if (horiz) { int k = g >> 1, hf = g & 1;  return k * HW + base0 + 4 * hf; }
        else       { int L = g >> 6, k4 = g & 63; return (base0 + L) * HW + 4 * k4; }
    };

    Stage sA, sB;
    // ---- prologue: LDG tiles 0,1; pack tile 0 -> packed[0] ----
    if (g >= 0) {
        ldg_tile(sA, gaddr(tbase(0)), mb, g1b, g2b, g3b);
        ldg_tile(sB, gaddr(tbase(1)), mb, g1b, g2b, g3b);
        sts_tile(sA, packed, horiz, g);
    }
    float h[8];
    #pragma unroll
    for (int e = 0; e < 8; ++e) h[e] = 0.f;
    __syncthreads();

    // ---- main loop: 2 tiles per iteration, ONE barrier per tile ----
    for (int t = 0; t < NTILES; t += 2) {
        // even: scan packed[0]=t; loaders: LDG t+2 -> sA, STS sB(t+1) -> packed[1]
        if (tid < 32) {
            scan_tile(packed, h, scr, tbase(t), rev, lane);
        } else {
            if (t + 2 < NTILES)
                ldg_tile(sA, gaddr(tbase(t + 2)), mb, g1b, g2b, g3b);
            sts_tile(sB, packed + PBUF, horiz, g);
        }
        __syncthreads();

        // odd: scan packed[1]=t+1; loaders: LDG t+3 -> sB, STS sA(t+2) -> packed[0]
        if (tid < 32) {
            scan_tile(packed + PBUF, h, scr, tbase(t + 1), rev, lane);
        } else if (t + 2 < NTILES) {
            if (t + 3 < NTILES)
                ldg_tile(sB, gaddr(tbase(t + 3)), mb, g1b, g2b, g3b);
            sts_tile(sA, packed, horiz, g);
        }
        __syncthreads();
    }
}

// out(h,w) = max over 4 dirs; dirs 0,1 transposed in fp16 scratch.
__global__ __launch_bounds__(256) void spn_max(float* __restrict__ out)
{
    __shared__ float t0[32][33], t1[32][33];
    const int bc   = blockIdx.x >> 6;
    const int tile = blockIdx.x & 63;
    const int h0 = (tile >> 3) * 32, w0 = (tile & 7) * 32;
    const int r = threadIdx.x >> 3;        // 0..31
    const int q = threadIdx.x & 7;         // 0..7
    const __half* S = g_scratch + (size_t)bc * 4 * PLANE;

    // transposed planes: row = w, contiguous in h -> 8B loads of 4 halves
    {
        int w = w0 + r;
        const __half2* s0 = (const __half2*)(S + 0 * PLANE + w * HW + h0 + 4 * q);
        const __half2* s1 = (const __half2*)(S + 1 * PLANE + w * HW + h0 + 4 * q);
        float2 a0 = __half22float2(s0[0]), a1 = __half22float2(s0[1]);
        float2 b0 = __half22float2(s1[0]), b1 = __half22float2(s1[1]);
        t0[r][4 * q + 0] = a0.x; t0[r][4 * q + 1] = a0.y;
        t0[r][4 * q + 2] = a1.x; t0[r][4 * q + 3] = a1.y;
        t1[r][4 * q + 0] = b0.x; t1[r][4 * q + 1] = b0.y;
        t1[r][4 * q + 2] = b1.x; t1[r][4 * q + 3] = b1.y;
    }
    __syncthreads();

    int h = h0 + r;
    int gbase = h * HW + w0 + 4 * q;
    const __half2* s2 = (const __half2*)(S + 2 * PLANE + gbase);
    const __half2* s3 = (const __half2*)(S + 3 * PLANE + gbase);
    float2 c0 = __half22float2(s2[0]), c1 = __half22float2(s2[1]);
    float2 d0 = __half22float2(s3[0]), d1 = __half22float2(s3[1]);
    float4 v;
    v.x = fmaxf(fmaxf(c0.x, d0.x), fmaxf(t0[4 * q + 0][r], t1[4 * q + 0][r]));
    v.y = fmaxf(fmaxf(c0.y, d0.y), fmaxf(t0[4 * q + 1][r], t1[4 * q + 1][r]));
    v.z = fmaxf(fmaxf(c1.x, d1.x), fmaxf(t0[4 * q + 2][r], t1[4 * q + 2][r]));
    v.w = fmaxf(fmaxf(c1.y, d1.y), fmaxf(t0[4 * q + 3][r], t1[4 * q + 3][r]));
    *(float4*)(out + (size_t)bc * PLANE + gbase) = v;
}

extern "C" void kernel_launch(void* const* d_in, const int* in_sizes, int n_in,
                              void* d_out, int out_size) {
    const float* x    = (const float*)d_in[0];
    const float* mask = (const float*)d_in[1];
    if (n_in >= 2 && in_sizes[0] < in_sizes[1]) {   // defensive: x is 12x mask
        x    = (const float*)d_in[1];
        mask = (const float*)d_in[0];
    }
    size_t smem = (size_t)2 * PBUF * sizeof(float4);   // 75,008 B
    cudaFuncSetAttribute(spn_scan, cudaFuncAttributeMaxDynamicSharedMemorySize, (int)smem);
    spn_scan<<<512, NT, smem>>>(x, mask);
    spn_max<<<128 * 64, 256>>>((float*)d_out);
}

// round 14
// speedup vs baseline: 1.3092x; 1.3092x over previous
#include <cuda_runtime.h>
#include <cuda_fp16.h>
#include <cstdint>

#define HW 256
#define PLANE (HW * HW)
#define TILE 8
#define NT 288                // warp0 = scanner; warps 1..8 = 256 loaders
#define NTILES (HW / TILE)    // 32
#define ROWSLOT 264           // 8B slots per packed row (256 + 8 pad)
#define PROW (ROWSLOT)        // slots
#define PBUF (TILE * ROWSLOT) // slots per packed buffer (2112) -> 16,896 B
#define SLOT_F4 2048          // float4s per ring slot (4 arrays x 512) = 32,768 B

// Per-(plane,dir) fp16 scratch, plane index = bc*4 + dir (67 MB).
// dirs 0,1 (horizontal) stored TRANSPOSED [w][h]; dirs 2,3 natural [h][w].
__device__ __half g_scratch[512 * PLANE];

struct alignas(16) H8 { __half2 p0, p1, p2, p3; };
struct alignas(8) PK { __half2 pa, bc; };     // packed gate element, 8 B

// element k -> conflict-free 8B slot within a packed row
__device__ __forceinline__ int kslot(int k) { return (k & 7) * 33 + (k >> 3); }

__device__ __forceinline__ PK gate_pack(float m, float g1, float g2, float g3) {
    float s = fabsf(g1) + fabsf(g2) + fabsf(g3) + 1e-7f;
    float r = (s >= 1.f) ? __fdividef(1.f, s) : 1.f;
    float a = g1 * r, b = g2 * r, c = g3 * r;
    PK o;
    o.pa = __floats2half2_rn((1.f - a - b - c) * m, a);
    o.bc = __floats2half2_rn(b, c);
    return o;
}

__device__ __forceinline__ void cp16(unsigned int dst, const float* src) {
    asm volatile("cp.async.cg.shared.global [%0], [%1], 16;\n" :: "r"(dst), "l"(src));
}
#define CP_COMMIT() asm volatile("cp.async.commit_group;\n" ::: "memory")
#define CP_WAIT1()  asm volatile("cp.async.wait_group 1;\n" ::: "memory")

// Issue one tile's 16B chunks into a ring slot (loader lt: 2 chunks x 4 arrays).
__device__ __forceinline__ void issue_tile(
    unsigned int raw_u32, int slot, int base0, bool horiz, int lt,
    const float* __restrict__ mb, const float* __restrict__ g1b,
    const float* __restrict__ g2b, const float* __restrict__ g3b)
{
    #pragma unroll
    for (int i = 0; i < 2; ++i) {
        int g = lt + i * 256;
        int ga;
        if (horiz) { int k = g >> 1, hf = g & 1;  ga = k * HW + base0 + 4 * hf; }
        else       { int L = g >> 6, k4 = g & 63; ga = (base0 + L) * HW + 4 * k4; }
        unsigned int d = raw_u32 + (unsigned int)slot * 32768u + (unsigned int)g * 16u;
        cp16(d,          mb  + ga);
        cp16(d +  8192u, g1b + ga);
        cp16(d + 16384u, g2b + ga);
        cp16(d + 24576u, g3b + ga);
    }
}

// Repack one tile from a raw ring slot into a packed fp16 buffer.
__device__ __forceinline__ void repack_tile(
    const float4* __restrict__ raw, PK* __restrict__ packed, bool horiz, int lt)
{
    #pragma unroll
    for (int i = 0; i < 2; ++i) {
        int g = lt + i * 256;
        float4 M = raw[0 * 512 + g];
        float4 A = raw[1 * 512 + g];
        float4 B = raw[2 * 512 + g];
        float4 C = raw[3 * 512 + g];
        const float* Mp = (const float*)&M;
        const float* Ap = (const float*)&A;
        const float* Bp = (const float*)&B;
        const float* Cp = (const float*)&C;
        if (horiz) {
            int k = g >> 1, hf = g & 1;
            int sl = kslot(k), L0 = 4 * hf;
            #pragma unroll
            for (int j = 0; j < 4; ++j)
                packed[(L0 + j) * PROW + sl] = gate_pack(Mp[j], Ap[j], Bp[j], Cp[j]);
        } else {
            int L = g >> 6, k4 = g & 63;
            PK* row = packed + L * PROW;
            #pragma unroll
            for (int j = 0; j < 4; ++j)
                row[kslot(4 * k4 + j)] = gate_pack(Mp[j], Ap[j], Bp[j], Cp[j]);
        }
    }
}

__global__ __launch_bounds__(NT, 2) void spn_scan(
    const float* __restrict__ x,
    const float* __restrict__ mask)
{
    extern __shared__ char smemc[];
    PK*     packed = (PK*)smemc;                       // [2][TILE][ROWSLOT]
    float4* raw    = (float4*)(smemc + 2 * PBUF * sizeof(PK));  // ring [2][4][512]
    unsigned int raw_u32 = (unsigned int)__cvta_generic_to_shared(raw);

    const int tid = threadIdx.x;
    const int blk = blockIdx.x;
    const int dir = blk & 3;                           // interleave dirs -> mask L2 reuse
    const int bc  = blk >> 2;
    const int b   = bc >> 5;
    const int c   = bc & 31;
    const bool horiz = (dir < 2);
    const bool rev   = (dir & 1);

    const float* mb  = mask + (size_t)bc * PLANE;
    const float* g1b = x + (size_t)(b * 384 + (3 * dir + 0) * 32 + c) * PLANE;
    const float* g2b = x + (size_t)(b * 384 + (3 * dir + 1) * 32 + c) * PLANE;
    const float* g3b = x + (size_t)(b * 384 + (3 * dir + 2) * 32 + c) * PLANE;
    __half* scr = g_scratch + (size_t)blk * PLANE;

    const int lane = tid & 31;
    const int lt   = tid - 32;                         // loader id 0..255 (scanner: <0)

    auto tbase = [&](int t) { return rev ? (HW - TILE - TILE * t) : (TILE * t); };

    // ---- prologue: tiles 0,1 in flight; repack tile 0 -> packed[0] ----
    if (lt >= 0) {
        issue_tile(raw_u32, 0, tbase(0), horiz, lt, mb, g1b, g2b, g3b); CP_COMMIT();
        issue_tile(raw_u32, 1, tbase(1), horiz, lt, mb, g1b, g2b, g3b); CP_COMMIT();
        CP_WAIT1();                                    // tile 0 complete
        repack_tile(raw, packed, horiz, lt);
    }
    float h[8];
    #pragma unroll
    for (int e = 0; e < 8; ++e) h[e] = 0.f;
    __syncthreads();

    // ---- main loop: ONE barrier per tile ----
    for (int t = 0; t < NTILES; ++t) {
        if (tid < 32) {
            const int base0 = tbase(t);
            const PK* pk = packed + (size_t)(t & 1) * PBUF;
            #pragma unroll
            for (int st = 0; st < TILE; ++st) {
                int L = rev ? (TILE - 1 - st) : st;
                const PK* row = pk + L * PROW;
                // 8 conflict-free LDS.64: lane reads slots 33e + lane
                PK q0 = row[lane], q1 = row[33 + lane], q2 = row[66 + lane], q3 = row[99 + lane];
                PK q4 = row[132 + lane], q5 = row[165 + lane], q6 = row[198 + lane], q7 = row[231 + lane];
                float2 pa0 = __half22float2(q0.pa), bc0 = __half22float2(q0.bc);
                float2 pa1 = __half22float2(q1.pa), bc1 = __half22float2(q1.bc);
                float2 pa2 = __half22float2(q2.pa), bc2 = __half22float2(q2.bc);
                float2 pa3 = __half22float2(q3.pa), bc3 = __half22float2(q3.bc);
                float2 pa4 = __half22float2(q4.pa), bc4 = __half22float2(q4.bc);
                float2 pa5 = __half22float2(q5.pa), bc5 = __half22float2(q5.bc);
                float2 pa6 = __half22float2(q6.pa), bc6 = __half22float2(q6.bc);
                float2 pa7 = __half22float2(q7.pa), bc7 = __half22float2(q7.bc);
                float hm = __shfl_up_sync(0xffffffffu, h[7], 1);
                float hp = __shfl_down_sync(0xffffffffu, h[0], 1);
                if (lane == 0)  hm = 0.f;
                if (lane == 31) hp = 0.f;
                float hn[8];
                hn[0] = fmaf(bc0.y, h[1], fmaf(bc0.x, h[0], fmaf(pa0.y, hm,   pa0.x)));
                hn[1] = fmaf(bc1.y, h[2], fmaf(bc1.x, h[1], fmaf(pa1.y, h[0], pa1.x)));
                hn[2] = fmaf(bc2.y, h[3], fmaf(bc2.x, h[2], fmaf(pa2.y, h[1], pa2.x)));
                hn[3] = fmaf(bc3.y, h[4], fmaf(bc3.x, h[3], fmaf(pa3.y, h[2], pa3.x)));
                hn[4] = fmaf(bc4.y, h[5], fmaf(bc4.x, h[4], fmaf(pa4.y, h[3], pa4.x)));
                hn[5] = fmaf(bc5.y, h[6], fmaf(bc5.x, h[5], fmaf(pa5.y, h[4], pa5.x)));
                hn[6] = fmaf(bc6.y, h[7], fmaf(bc6.x, h[6], fmaf(pa6.y, h[5], pa6.x)));
                hn[7] = fmaf(bc7.y, hp,   fmaf(bc7.x, h[7], fmaf(pa7.y, h[6], pa7.x)));
                #pragma unroll
                for (int e = 0; e < 8; ++e) h[e] = hn[e];
                H8 v;
                v.p0 = __floats2half2_rn(h[0], h[1]);
                v.p1 = __floats2half2_rn(h[2], h[3]);
                v.p2 = __floats2half2_rn(h[4], h[5]);
                v.p3 = __floats2half2_rn(h[6], h[7]);
                *(H8*)(scr + (base0 + L) * HW + 8 * lane) = v;   // 16B coalesced
            }
        } else {
            if (t + 2 < NTILES)
                issue_tile(raw_u32, t & 1, tbase(t + 2), horiz, lt, mb, g1b, g2b, g3b);
            CP_COMMIT();                               // exactly one group per iter
            if (t + 1 < NTILES) {
                CP_WAIT1();                            // tile t+1 data complete
                repack_tile(raw + (size_t)((t + 1) & 1) * SLOT_F4,
                            packed + (size_t)((t + 1) & 1) * PBUF, horiz, lt);
            }
        }
        __syncthreads();                               // join: packed[(t+1)&1] ready
    }
}

// out(h,w) = max over 4 dirs; dirs 0,1 transposed in fp16 scratch.
__global__ __launch_bounds__(256) void spn_max(float* __restrict__ out)
{
    __shared__ float t0[32][33], t1[32][33];
    const int bc   = blockIdx.x >> 6;
    const int tile = blockIdx.x & 63;
    const int h0 = (tile >> 3) * 32, w0 = (tile & 7) * 32;
    const int r = threadIdx.x >> 3;        // 0..31
    const int q = threadIdx.x & 7;         // 0..7
    const __half* S = g_scratch + (size_t)bc * 4 * PLANE;

    {
        int w = w0 + r;
        const __half2* s0 = (const __half2*)(S + 0 * PLANE + w * HW + h0 + 4 * q);
        const __half2* s1 = (const __half2*)(S + 1 * PLANE + w * HW + h0 + 4 * q);
        float2 a0 = __half22float2(s0[0]), a1 = __half22float2(s0[1]);
        float2 b0 = __half22float2(s1[0]), b1 = __half22float2(s1[1]);
        t0[r][4 * q + 0] = a0.x; t0[r][4 * q + 1] = a0.y;
        t0[r][4 * q + 2] = a1.x; t0[r][4 * q + 3] = a1.y;
        t1[r][4 * q + 0] = b0.x; t1[r][4 * q + 1] = b0.y;
        t1[r][4 * q + 2] = b1.x; t1[r][4 * q + 3] = b1.y;
    }
    __syncthreads();

    int h = h0 + r;
    int gbase = h * HW + w0 + 4 * q;
    const __half2* s2 = (const __half2*)(S + 2 * PLANE + gbase);
    const __half2* s3 = (const __half2*)(S + 3 * PLANE + gbase);
    float2 c0 = __half22float2(s2[0]), c1 = __half22float2(s2[1]);
    float2 d0 = __half22float2(s3[0]), d1 = __half22float2(s3[1]);
    float4 v;
    v.x = fmaxf(fmaxf(c0.x, d0.x), fmaxf(t0[4 * q + 0][r], t1[4 * q + 0][r]));
    v.y = fmaxf(fmaxf(c0.y, d0.y), fmaxf(t0[4 * q + 1][r], t1[4 * q + 1][r]));
    v.z = fmaxf(fmaxf(c1.x, d1.x), fmaxf(t0[4 * q + 2][r], t1[4 * q + 2][r]));
    v.w = fmaxf(fmaxf(c1.y, d1.y), fmaxf(t0[4 * q + 3][r], t1[4 * q + 3][r]));
    *(float4*)(out + (size_t)bc * PLANE + gbase) = v;
}

extern "C" void kernel_launch(void* const* d_in, const int* in_sizes, int n_in,
                              void* d_out, int out_size) {
    const float* x    = (const float*)d_in[0];
    const float* mask = (const float*)d_in[1];
    if (n_in >= 2 && in_sizes[0] < in_sizes[1]) {   // defensive: x is 12x mask
        x    = (const float*)d_in[1];
        mask = (const float*)d_in[0];
    }
    size_t smem = (size_t)2 * PBUF * sizeof(PK)        // packed x2: 33,792 B
                + 2u * SLOT_F4 * sizeof(float4);       // ring:      65,536 B
    cudaFuncSetAttribute(spn_scan, cudaFuncAttributeMaxDynamicSharedMemorySize, (int)smem);
    spn_scan<<<512, NT, smem>>>(x, mask);
    spn_max<<<128 * 64, 256>>>((float*)d_out);
}

// round 15
// speedup vs baseline: 1.4336x; 1.0950x over previous
#include <cuda_runtime.h>
#include <cuda_fp16.h>
#include <cstdint>

#define HW 256
#define PLANE (HW * HW)
#define TILE 16
#define NT 288                // warp0 = scanner; warps 1..8 = 256 loaders
#define NTILES (HW / TILE)    // 16
#define PROW 264              // 8B slots per packed row (33*8)
#define PBUF (TILE * PROW)    // slots per packed buffer (4224) -> 33,792 B
#define SLOT_F4 4096          // float4s per ring slot (4 arrays x 1024) = 65,536 B

// Per-(plane,dir) fp16 scratch, plane index = bc*4 + dir (67 MB).
// dirs 0,1 (horizontal) stored TRANSPOSED [w][h]; dirs 2,3 natural [h][w].
__device__ __half g_scratch[512 * PLANE];

struct alignas(16) H8 { __half2 p0, p1, p2, p3; };
struct alignas(8) PK { __half2 pa, bc; };     // packed gate element, 8 B

// element k -> conflict-free 8B slot within a packed row
__device__ __forceinline__ int kslot(int k) { return (k & 7) * 33 + (k >> 3); }

__device__ __forceinline__ PK gate_pack(float m, float g1, float g2, float g3) {
    float s = fabsf(g1) + fabsf(g2) + fabsf(g3) + 1e-7f;
    float r = (s >= 1.f) ? __fdividef(1.f, s) : 1.f;
    float a = g1 * r, b = g2 * r, c = g3 * r;
    PK o;
    o.pa = __floats2half2_rn((1.f - a - b - c) * m, a);
    o.bc = __floats2half2_rn(b, c);
    return o;
}

__device__ __forceinline__ void cp16(unsigned int dst, const float* src) {
    asm volatile("cp.async.cg.shared.global [%0], [%1], 16;\n" :: "r"(dst), "l"(src));
}
#define CP_COMMIT() asm volatile("cp.async.commit_group;\n" ::: "memory")
#define CP_WAIT1()  asm volatile("cp.async.wait_group 1;\n" ::: "memory")

// Issue one 16-step tile into a ring slot (loader lt: 4 chunks x 4 arrays).
// Horizontal rows fetch 64B contiguous (4 x 16B) -> better DRAM locality.
__device__ __forceinline__ void issue_tile(
    unsigned int raw_u32, int slot, int base0, bool horiz, int lt,
    const float* __restrict__ mb, const float* __restrict__ g1b,
    const float* __restrict__ g2b, const float* __restrict__ g3b)
{
    #pragma unroll
    for (int i = 0; i < 4; ++i) {
        int g = lt + i * 256;                  // group 0..1023
        int ga;
        if (horiz) { int k = g >> 2, hf = g & 3;  ga = k * HW + base0 + 4 * hf; }
        else       { int L = g >> 6, k4 = g & 63; ga = (base0 + L) * HW + 4 * k4; }
        unsigned int d = raw_u32 + (unsigned int)slot * 65536u + (unsigned int)g * 16u;
        cp16(d,           mb  + ga);
        cp16(d + 16384u,  g1b + ga);
        cp16(d + 32768u,  g2b + ga);
        cp16(d + 49152u,  g3b + ga);
    }
}

// Repack one tile from a raw ring slot into a packed fp16 buffer.
__device__ __forceinline__ void repack_tile(
    const float4* __restrict__ raw, PK* __restrict__ packed, bool horiz, int lt)
{
    #pragma unroll
    for (int i = 0; i < 4; ++i) {
        int g = lt + i * 256;
        float4 M = raw[0 * 1024 + g];
        float4 A = raw[1 * 1024 + g];
        float4 B = raw[2 * 1024 + g];
        float4 C = raw[3 * 1024 + g];
        const float* Mp = (const float*)&M;
        const float* Ap = (const float*)&A;
        const float* Bp = (const float*)&B;
        const float* Cp = (const float*)&C;
        if (horiz) {
            int k = g >> 2, hf = g & 3;
            int sl = kslot(k), L0 = 4 * hf;
            #pragma unroll
            for (int j = 0; j < 4; ++j)
                packed[(L0 + j) * PROW + sl] = gate_pack(Mp[j], Ap[j], Bp[j], Cp[j]);
        } else {
            int L = g >> 6, k4 = g & 63;
            PK* row = packed + L * PROW;
            #pragma unroll
            for (int j = 0; j < 4; ++j)
                row[kslot(4 * k4 + j)] = gate_pack(Mp[j], Ap[j], Bp[j], Cp[j]);
        }
    }
}

__global__ __launch_bounds__(NT, 1) void spn_scan(
    const float* __restrict__ x,
    const float* __restrict__ mask)
{
    extern __shared__ char smemc[];
    PK*     packed = (PK*)smemc;                                // [2][TILE][PROW]
    float4* raw    = (float4*)(smemc + 2 * PBUF * sizeof(PK));  // ring [2][4][1024]
    unsigned int raw_u32 = (unsigned int)__cvta_generic_to_shared(raw);

    const int tid = threadIdx.x;
    const int blk = blockIdx.x;
    const int dir = blk & 3;                           // interleave dirs -> mask L2 reuse
    const int bc  = blk >> 2;
    const int b   = bc >> 5;
    const int c   = bc & 31;
    const bool horiz = (dir < 2);
    const bool rev   = (dir & 1);

    const float* mb  = mask + (size_t)bc * PLANE;
    const float* g1b = x + (size_t)(b * 384 + (3 * dir + 0) * 32 + c) * PLANE;
    const float* g2b = x + (size_t)(b * 384 + (3 * dir + 1) * 32 + c) * PLANE;
    const float* g3b = x + (size_t)(b * 384 + (3 * dir + 2) * 32 + c) * PLANE;
    __half* scr = g_scratch + (size_t)blk * PLANE;

    const int lane = tid & 31;
    const int lt   = tid - 32;                         // loader id 0..255 (scanner: <0)

    auto tbase = [&](int t) { return rev ? (HW - TILE - TILE * t) : (TILE * t); };

    // ---- prologue: tiles 0,1 in flight; repack tile 0 -> packed[0] ----
    if (lt >= 0) {
        issue_tile(raw_u32, 0, tbase(0), horiz, lt, mb, g1b, g2b, g3b); CP_COMMIT();
        issue_tile(raw_u32, 1, tbase(1), horiz, lt, mb, g1b, g2b, g3b); CP_COMMIT();
        CP_WAIT1();                                    // tile 0 complete
        repack_tile(raw, packed, horiz, lt);
    }
    float h[8];
    #pragma unroll
    for (int e = 0; e < 8; ++e) h[e] = 0.f;
    __syncthreads();

    // ---- main loop: ONE barrier per tile ----
    for (int t = 0; t < NTILES; ++t) {
        if (tid < 32) {
            const int base0 = tbase(t);
            const PK* pk = packed + (size_t)(t & 1) * PBUF;
            #pragma unroll
            for (int st = 0; st < TILE; ++st) {
                int L = rev ? (TILE - 1 - st) : st;
                const PK* row = pk + L * PROW;
                PK q0 = row[lane],       q1 = row[33 + lane],  q2 = row[66 + lane],  q3 = row[99 + lane];
                PK q4 = row[132 + lane], q5 = row[165 + lane], q6 = row[198 + lane], q7 = row[231 + lane];
                float2 pa0 = __half22float2(q0.pa), bc0 = __half22float2(q0.bc);
                float2 pa1 = __half22float2(q1.pa), bc1 = __half22float2(q1.bc);
                float2 pa2 = __half22float2(q2.pa), bc2 = __half22float2(q2.bc);
                float2 pa3 = __half22float2(q3.pa), bc3 = __half22float2(q3.bc);
                float2 pa4 = __half22float2(q4.pa), bc4 = __half22float2(q4.bc);
                float2 pa5 = __half22float2(q5.pa), bc5 = __half22float2(q5.bc);
                float2 pa6 = __half22float2(q6.pa), bc6 = __half22float2(q6.bc);
                float2 pa7 = __half22float2(q7.pa), bc7 = __half22float2(q7.bc);
                float hm = __shfl_up_sync(0xffffffffu, h[7], 1);
                float hp = __shfl_down_sync(0xffffffffu, h[0], 1);
                if (lane == 0)  hm = 0.f;
                if (lane == 31) hp = 0.f;
                float hn[8];
                hn[0] = fmaf(bc0.y, h[1], fmaf(bc0.x, h[0], fmaf(pa0.y, hm,   pa0.x)));
                hn[1] = fmaf(bc1.y, h[2], fmaf(bc1.x, h[1], fmaf(pa1.y, h[0], pa1.x)));
                hn[2] = fmaf(bc2.y, h[3], fmaf(bc2.x, h[2], fmaf(pa2.y, h[1], pa2.x)));
                hn[3] = fmaf(bc3.y, h[4], fmaf(bc3.x, h[3], fmaf(pa3.y, h[2], pa3.x)));
                hn[4] = fmaf(bc4.y, h[5], fmaf(bc4.x, h[4], fmaf(pa4.y, h[3], pa4.x)));
                hn[5] = fmaf(bc5.y, h[6], fmaf(bc5.x, h[5], fmaf(pa5.y, h[4], pa5.x)));
                hn[6] = fmaf(bc6.y, h[7], fmaf(bc6.x, h[6], fmaf(pa6.y, h[5], pa6.x)));
                hn[7] = fmaf(bc7.y, hp,   fmaf(bc7.x, h[7], fmaf(pa7.y, h[6], pa7.x)));
                #pragma unroll
                for (int e = 0; e < 8; ++e) h[e] = hn[e];
                H8 v;
                v.p0 = __floats2half2_rn(h[0], h[1]);
                v.p1 = __floats2half2_rn(h[2], h[3]);
                v.p2 = __floats2half2_rn(h[4], h[5]);
                v.p3 = __floats2half2_rn(h[6], h[7]);
                *(H8*)(scr + (base0 + L) * HW + 8 * lane) = v;   // 16B coalesced
            }
        } else {
            if (t + 2 < NTILES)
                issue_tile(raw_u32, t & 1, tbase(t + 2), horiz, lt, mb, g1b, g2b, g3b);
            CP_COMMIT();                               // exactly one group per iter
            if (t + 1 < NTILES) {
                CP_WAIT1();                            // tile t+1 data complete
                repack_tile(raw + (size_t)((t + 1) & 1) * SLOT_F4,
                            packed + (size_t)((t + 1) & 1) * PBUF, horiz, lt);
            }
        }
        __syncthreads();                               // join: packed[(t+1)&1] ready
    }
}

// out(h,w) = max over 4 dirs; dirs 0,1 transposed in fp16 scratch.
__global__ __launch_bounds__(256) void spn_max(float* __restrict__ out)
{
    __shared__ float t0[32][33], t1[32][33];
    const int bc   = blockIdx.x >> 6;
    const int tile = blockIdx.x & 63;
    const int h0 = (tile >> 3) * 32, w0 = (tile & 7) * 32;
    const int r = threadIdx.x >> 3;        // 0..31
    const int q = threadIdx.x & 7;         // 0..7
    const __half* S = g_scratch + (size_t)bc * 4 * PLANE;

    {
        int w = w0 + r;
        const __half2* s0 = (const __half2*)(S + 0 * PLANE + w * HW + h0 + 4 * q);
        const __half2* s1 = (const __half2*)(S + 1 * PLANE + w * HW + h0 + 4 * q);
        float2 a0 = __half22float2(s0[0]), a1 = __half22float2(s0[1]);
        float2 b0 = __half22float2(s1[0]), b1 = __half22float2(s1[1]);
        t0[r][4 * q + 0] = a0.x; t0[r][4 * q + 1] = a0.y;
        t0[r][4 * q + 2] = a1.x; t0[r][4 * q + 3] = a1.y;
        t1[r][4 * q + 0] = b0.x; t1[r][4 * q + 1] = b0.y;
        t1[r][4 * q + 2] = b1.x; t1[r][4 * q + 3] = b1.y;
    }
    __syncthreads();

    int h = h0 + r;
    int gbase = h * HW + w0 + 4 * q;
    const __half2* s2 = (const __half2*)(S + 2 * PLANE + gbase);
    const __half2* s3 = (const __half2*)(S + 3 * PLANE + gbase);
    float2 c0 = __half22float2(s2[0]), c1 = __half22float2(s2[1]);
    float2 d0 = __half22float2(s3[0]), d1 = __half22float2(s3[1]);
    float4 v;
    v.x = fmaxf(fmaxf(c0.x, d0.x), fmaxf(t0[4 * q + 0][r], t1[4 * q + 0][r]));
    v.y = fmaxf(fmaxf(c0.y, d0.y), fmaxf(t0[4 * q + 1][r], t1[4 * q + 1][r]));
    v.z = fmaxf(fmaxf(c1.x, d1.x), fmaxf(t0[4 * q + 2][r], t1[4 * q + 2][r]));
    v.w = fmaxf(fmaxf(c1.y, d1.y), fmaxf(t0[4 * q + 3][r], t1[4 * q + 3][r]));
    *(float4*)(out + (size_t)bc * PLANE + gbase) = v;
}

extern "C" void kernel_launch(void* const* d_in, const int* in_sizes, int n_in,
                              void* d_out, int out_size) {
    const float* x    = (const float*)d_in[0];
    const float* mask = (const float*)d_in[1];
    if (n_in >= 2 && in_sizes[0] < in_sizes[1]) {   // defensive: x is 12x mask
        x    = (const float*)d_in[1];
        mask = (const float*)d_in[0];
    }
    size_t smem = (size_t)2 * PBUF * sizeof(PK)        // packed x2: 67,584 B
                + 2u * SLOT_F4 * sizeof(float4);       // ring:     131,072 B
    cudaFuncSetAttribute(spn_scan, cudaFuncAttributeMaxDynamicSharedMemorySize, (int)smem);
    spn_scan<<<512, NT, smem>>>(x, mask);
    spn_max<<<128 * 64, 256>>>((float*)d_out);
}